// round 5
// baseline (speedup 1.0000x reference)
#include <cuda_runtime.h>

#define BATCH 4
#define S_LEN 2048
#define HDIM  1024
#define NHQ   16
#define NKV   4
#define HD    64
#define SCALE 0.125f

// ---------------- device scratch (no cudaMalloc allowed) ----------------
__device__ float g_Q[(size_t)BATCH * NHQ * S_LEN * HD];   // [b, h, s, d]
__device__ float g_K[(size_t)BATCH * NKV * S_LEN * HD];   // [b, kvh, s, d]
__device__ float g_V[(size_t)BATCH * NKV * S_LEN * HD];   // [b, kvh, s, d]
__device__ float g_attn[(size_t)BATCH * S_LEN * NHQ * HD]; // [b, s, h*HD]

// ---------------- tf32 helpers ----------------
__device__ __forceinline__ unsigned f2tf32(float x) {
    unsigned r;
    asm("cvt.rna.tf32.f32 %0, %1;" : "=r"(r) : "f"(x));
    return r;
}
__device__ __forceinline__ void split_tf32(float x, unsigned& hi, unsigned& lo) {
    hi = f2tf32(x);
    lo = f2tf32(x - __uint_as_float(hi));
}
__device__ __forceinline__ void mma_tf32(float c[4], const unsigned a[4],
                                         unsigned b0, unsigned b1) {
    asm volatile(
        "mma.sync.aligned.m16n8k8.row.col.f32.tf32.tf32.f32 "
        "{%0,%1,%2,%3},{%4,%5,%6,%7},{%8,%9},{%0,%1,%2,%3};"
        : "+f"(c[0]), "+f"(c[1]), "+f"(c[2]), "+f"(c[3])
        : "r"(a[0]), "r"(a[1]), "r"(a[2]), "r"(a[3]), "r"(b0), "r"(b1));
}

// ---------------- 128x128x32 GEMM via 3xTF32 mma.sync -------------------
// scatter==1: C is [b, head, s, d] with given head count (QKV projections)
// scatter==0: C is plain row-major MxN (output projection)
#define ASTRIDE 36    // 36 mod 32 = 4  -> frag bank = lane (conflict-free w/ swizzle)
#define BSTRIDE 136   // 136 mod 32 = 8 -> frag bank = 8c+r (conflict-free)

__global__ __launch_bounds__(256) void gemm_tf32_kernel(
    const float* __restrict__ A, const float* __restrict__ B,
    float* __restrict__ C, int M, int N, int K, int scatter, int heads)
{
    __shared__ float As[128][ASTRIDE];
    __shared__ float Bs[32][BSTRIDE];

    const int bm = blockIdx.y << 7;
    const int bn = blockIdx.x << 7;
    const int tid = threadIdx.x;
    const int lane = tid & 31;
    const int warp = tid >> 5;
    const int wm = warp & 3;        // 4 warps along M, 32 rows each
    const int wn = warp >> 2;       // 2 warps along N, 64 cols each

    // staging maps
    const int arow = tid >> 3;            // 0..31 (+32*i)
    const int ac4  = tid & 7;             // float4 col index in A tile
    const int brow = tid >> 5;            // 0..7 (+8*i)
    const int bc4  = tid & 31;            // float4 col index in B tile

    float acc[2][8][4];
#pragma unroll
    for (int mt = 0; mt < 2; mt++)
#pragma unroll
        for (int nt = 0; nt < 8; nt++)
#pragma unroll
            for (int e = 0; e < 4; e++) acc[mt][nt][e] = 0.f;

    float4 aR[4], bR[4];
#pragma unroll
    for (int i = 0; i < 4; i++) {
        aR[i] = *(const float4*)(A + (size_t)(bm + arow + 32 * i) * K + ac4 * 4);
        bR[i] = *(const float4*)(B + (size_t)(brow + 8 * i) * N + bn + bc4 * 4);
    }

    for (int k0 = 0; k0 < K; k0 += 32) {
        // stage registers -> smem (A with col ^ (row&3) swizzle)
#pragma unroll
        for (int i = 0; i < 4; i++) {
            const int r = arow + 32 * i;
            const int rr = r & 3;
            float t[4] = {aR[i].x, aR[i].y, aR[i].z, aR[i].w};
#pragma unroll
            for (int j = 0; j < 4; j++)
                As[r][ac4 * 4 + (j ^ rr)] = t[j];
            *(float4*)(&Bs[brow + 8 * i][bc4 * 4]) = bR[i];
        }
        __syncthreads();

        if (k0 + 32 < K) {
#pragma unroll
            for (int i = 0; i < 4; i++) {
                aR[i] = *(const float4*)(A + (size_t)(bm + arow + 32 * i) * K + k0 + 32 + ac4 * 4);
                bR[i] = *(const float4*)(B + (size_t)(k0 + 32 + brow + 8 * i) * N + bn + bc4 * 4);
            }
        }

#pragma unroll
        for (int kk = 0; kk < 32; kk += 8) {
            unsigned ahi[2][4], alo[2][4];
#pragma unroll
            for (int mt = 0; mt < 2; mt++) {
                const int rA = wm * 32 + mt * 16 + (lane >> 2);
                const int cs = (lane & 3) ^ (rA & 3);   // swizzled low bits
                split_tf32(As[rA][kk + cs],         ahi[mt][0], alo[mt][0]);
                split_tf32(As[rA + 8][kk + cs],     ahi[mt][1], alo[mt][1]);
                split_tf32(As[rA][kk + 4 + cs],     ahi[mt][2], alo[mt][2]);
                split_tf32(As[rA + 8][kk + 4 + cs], ahi[mt][3], alo[mt][3]);
            }
#pragma unroll
            for (int nt = 0; nt < 8; nt++) {
                const int nc = wn * 64 + nt * 8 + (lane >> 2);
                unsigned bhi0, blo0, bhi1, blo1;
                split_tf32(Bs[kk + (lane & 3)][nc],     bhi0, blo0);
                split_tf32(Bs[kk + (lane & 3) + 4][nc], bhi1, blo1);
#pragma unroll
                for (int mt = 0; mt < 2; mt++) {
                    mma_tf32(acc[mt][nt], ahi[mt], blo0, blo1);   // small terms first
                    mma_tf32(acc[mt][nt], alo[mt], bhi0, bhi1);
                    mma_tf32(acc[mt][nt], ahi[mt], bhi0, bhi1);
                }
            }
        }
        __syncthreads();
    }

    // epilogue
#pragma unroll
    for (int mt = 0; mt < 2; mt++) {
#pragma unroll
        for (int nt = 0; nt < 8; nt++) {
            const int r0 = bm + wm * 32 + mt * 16 + (lane >> 2);
            const int cn = bn + wn * 64 + nt * 8 + (lane & 3) * 2;
            if (scatter) {
                const int head = cn >> 6, d = cn & 63;
#pragma unroll
                for (int half = 0; half < 2; half++) {
                    const int rm = r0 + half * 8;
                    const int b = rm >> 11, s = rm & 2047;
                    float* dst = C + (((size_t)(b * heads + head)) * S_LEN + s) * HD + d;
                    *(float2*)dst = make_float2(acc[mt][nt][half * 2], acc[mt][nt][half * 2 + 1]);
                }
            } else {
                *(float2*)(C + (size_t)r0 * N + cn) =
                    make_float2(acc[mt][nt][0], acc[mt][nt][1]);
                *(float2*)(C + (size_t)(r0 + 8) * N + cn) =
                    make_float2(acc[mt][nt][2], acc[mt][nt][3]);
            }
        }
    }
}

// ---------------- RMSNorm + interleaved RoPE, one warp per (row of HD=64) --
__global__ __launch_bounds__(256) void norm_rope_kernel(
    float* __restrict__ X, const float* __restrict__ w,
    const float* __restrict__ cosb, const float* __restrict__ sinb, int rows)
{
    const int row = blockIdx.x * 8 + threadIdx.y;
    if (row >= rows) return;
    const int lane = threadIdx.x;
    const int s = row & (S_LEN - 1);

    float2 x = *(float2*)(X + (size_t)row * HD + lane * 2);
    float ssq = x.x * x.x + x.y * x.y;
#pragma unroll
    for (int m = 16; m; m >>= 1) ssq += __shfl_xor_sync(0xffffffffu, ssq, m);
    const float inv = rsqrtf(ssq * (1.0f / 64.0f) + 1e-6f);

    const float n0 = x.x * inv * w[lane * 2];
    const float n1 = x.y * inv * w[lane * 2 + 1];
    const float c0 = cosb[(size_t)s * HD + lane * 2];
    const float c1 = cosb[(size_t)s * HD + lane * 2 + 1];
    const float s0 = sinb[(size_t)s * HD + lane * 2];
    const float s1 = sinb[(size_t)s * HD + lane * 2 + 1];

    float2 o;
    o.x = n0 * c0 - n1 * s0;   // x[2i]*cos - x[2i+1]*sin
    o.y = n1 * c1 + n0 * s1;   // x[2i+1]*cos + x[2i]*sin
    *(float2*)(X + (size_t)row * HD + lane * 2) = o;
}

// ---------------- flash attention (causal, GQA), 64-row Q tile -----------
__global__ __launch_bounds__(256) void flash_kernel(
    const float* __restrict__ Q, const float* __restrict__ K,
    const float* __restrict__ V, float* __restrict__ O)
{
    __shared__ float QsT[64][64];   // transposed: QsT[d][r]
    __shared__ float KsT[64][64];   // transposed: KsT[d][c]; reused as Ps[r][k]
    __shared__ float Vs[64][64];    // row-major: Vs[k][d]
    float (*Ps)[64] = KsT;

    const int bh = blockIdx.y;
    const int b = bh >> 4, h = bh & 15, kvh = (bh & 15) >> 2;
    const int i0 = blockIdx.x << 6;
    const float* Qb = Q + ((size_t)(b * NHQ + h) * S_LEN + i0) * HD;
    const float* Kb = K + (size_t)(b * NKV + kvh) * S_LEN * HD;
    const float* Vb = V + (size_t)(b * NKV + kvh) * S_LEN * HD;

    const int tid = threadIdx.x;
    const int tx = tid & 15, ty = tid >> 4;
    const int r0 = ty << 2, c0 = tx << 2;

    // load Q tile transposed
    for (int idx = tid; idx < 1024; idx += 256) {
        const int r = idx >> 4, d = (idx & 15) << 2;
        float4 v = *(const float4*)(Qb + (size_t)r * HD + d);
        QsT[d][r] = v.x; QsT[d + 1][r] = v.y; QsT[d + 2][r] = v.z; QsT[d + 3][r] = v.w;
    }

    float m_i[4] = {-1e30f, -1e30f, -1e30f, -1e30f};
    float l_i[4] = {0.f, 0.f, 0.f, 0.f};
    float oa[4][4];
#pragma unroll
    for (int i = 0; i < 4; i++)
#pragma unroll
        for (int j = 0; j < 4; j++) oa[i][j] = 0.f;

    const int ntiles = blockIdx.x + 1;
    for (int t = 0; t < ntiles; t++) {
        const int j0 = t << 6;
        __syncthreads();  // previous PV reads of Ps/Vs done
        for (int idx = tid; idx < 1024; idx += 256) {
            const int r = idx >> 4, d = (idx & 15) << 2;
            float4 kv = *(const float4*)(Kb + (size_t)(j0 + r) * HD + d);
            KsT[d][r] = kv.x; KsT[d + 1][r] = kv.y; KsT[d + 2][r] = kv.z; KsT[d + 3][r] = kv.w;
            *(float4*)(&Vs[r][d]) = *(const float4*)(Vb + (size_t)(j0 + r) * HD + d);
        }
        __syncthreads();

        // scores: sc[i][j] = Q[r0+i] . K[c0+j]
        float sc[4][4];
#pragma unroll
        for (int i = 0; i < 4; i++)
#pragma unroll
            for (int j = 0; j < 4; j++) sc[i][j] = 0.f;
#pragma unroll 8
        for (int d = 0; d < 64; d++) {
            float4 aq = *(const float4*)(&QsT[d][r0]);
            float4 bk = *(const float4*)(&KsT[d][c0]);
            sc[0][0] += aq.x * bk.x; sc[0][1] += aq.x * bk.y; sc[0][2] += aq.x * bk.z; sc[0][3] += aq.x * bk.w;
            sc[1][0] += aq.y * bk.x; sc[1][1] += aq.y * bk.y; sc[1][2] += aq.y * bk.z; sc[1][3] += aq.y * bk.w;
            sc[2][0] += aq.z * bk.x; sc[2][1] += aq.z * bk.y; sc[2][2] += aq.z * bk.z; sc[2][3] += aq.z * bk.w;
            sc[3][0] += aq.w * bk.x; sc[3][1] += aq.w * bk.y; sc[3][2] += aq.w * bk.z; sc[3][3] += aq.w * bk.w;
        }
        __syncthreads();  // done reading KsT (about to overwrite with Ps)

        const bool diag = (t == (int)blockIdx.x);
#pragma unroll
        for (int i = 0; i < 4; i++) {
#pragma unroll
            for (int j = 0; j < 4; j++) {
                float s = sc[i][j] * SCALE;
                if (diag && (c0 + j > r0 + i)) s = -1e9f;   // causal mask (matches ref)
                sc[i][j] = s;
            }
            float mt = fmaxf(fmaxf(sc[i][0], sc[i][1]), fmaxf(sc[i][2], sc[i][3]));
            mt = fmaxf(mt, __shfl_xor_sync(0xffffffffu, mt, 8));
            mt = fmaxf(mt, __shfl_xor_sync(0xffffffffu, mt, 4));
            mt = fmaxf(mt, __shfl_xor_sync(0xffffffffu, mt, 2));
            mt = fmaxf(mt, __shfl_xor_sync(0xffffffffu, mt, 1));
            const float m_new = fmaxf(m_i[i], mt);
            const float corr = __expf(m_i[i] - m_new);
            m_i[i] = m_new;
            float ps = 0.f;
#pragma unroll
            for (int j = 0; j < 4; j++) {
                const float p = __expf(sc[i][j] - m_new);
                sc[i][j] = p;
                ps += p;
            }
            ps += __shfl_xor_sync(0xffffffffu, ps, 8);
            ps += __shfl_xor_sync(0xffffffffu, ps, 4);
            ps += __shfl_xor_sync(0xffffffffu, ps, 2);
            ps += __shfl_xor_sync(0xffffffffu, ps, 1);
            l_i[i] = l_i[i] * corr + ps;
#pragma unroll
            for (int j = 0; j < 4; j++) oa[i][j] *= corr;
            *(float4*)(&Ps[r0 + i][c0]) = *(float4*)(&sc[i][0]);
        }
        __syncthreads();  // Ps visible

        // O += P @ V
#pragma unroll 8
        for (int k = 0; k < 64; k++) {
            float4 vv = *(const float4*)(&Vs[k][c0]);
#pragma unroll
            for (int i = 0; i < 4; i++) {
                const float p = Ps[r0 + i][k];
                oa[i][0] += p * vv.x; oa[i][1] += p * vv.y;
                oa[i][2] += p * vv.z; oa[i][3] += p * vv.w;
            }
        }
    }

    // normalize + write to [b, s, h*HD + d]
#pragma unroll
    for (int i = 0; i < 4; i++) {
        const float inv = 1.0f / l_i[i];
        float* dst = O + ((size_t)b * S_LEN + i0 + r0 + i) * (NHQ * HD) + h * HD + c0;
        *(float4*)dst = make_float4(oa[i][0] * inv, oa[i][1] * inv,
                                    oa[i][2] * inv, oa[i][3] * inv);
    }
}

// ---------------- launch ----------------
extern "C" void kernel_launch(void* const* d_in, const int* in_sizes, int n_in,
                              void* d_out, int out_size)
{
    const float* X    = (const float*)d_in[0];  // hidden_states [B,S,H]
    // d_in[1] causal_mask: implied by causal structure, unused
    const float* cosb = (const float*)d_in[2];
    const float* sinb = (const float*)d_in[3];
    const float* Wq   = (const float*)d_in[4];
    const float* Wk   = (const float*)d_in[5];
    const float* Wv   = (const float*)d_in[6];
    const float* Wo   = (const float*)d_in[7];
    const float* qw   = (const float*)d_in[8];
    const float* kw   = (const float*)d_in[9];
    float* out = (float*)d_out;

    void *pQ, *pK, *pV, *pA;
    cudaGetSymbolAddress(&pQ, g_Q);
    cudaGetSymbolAddress(&pK, g_K);
    cudaGetSymbolAddress(&pV, g_V);
    cudaGetSymbolAddress(&pA, g_attn);

    const int M = BATCH * S_LEN;  // 8192

    // QKV projections with scatter into [b, head, s, d]
    gemm_tf32_kernel<<<dim3(NHQ * HD / 128, M / 128), 256>>>(X, Wq, (float*)pQ, M, NHQ * HD, HDIM, 1, NHQ);
    gemm_tf32_kernel<<<dim3(NKV * HD / 128, M / 128), 256>>>(X, Wk, (float*)pK, M, NKV * HD, HDIM, 1, NKV);
    gemm_tf32_kernel<<<dim3(NKV * HD / 128, M / 128), 256>>>(X, Wv, (float*)pV, M, NKV * HD, HDIM, 1, NKV);

    // RMSNorm + RoPE on Q and K
    norm_rope_kernel<<<(BATCH * NHQ * S_LEN) / 8, dim3(32, 8)>>>((float*)pQ, qw, cosb, sinb, BATCH * NHQ * S_LEN);
    norm_rope_kernel<<<(BATCH * NKV * S_LEN) / 8, dim3(32, 8)>>>((float*)pK, kw, cosb, sinb, BATCH * NKV * S_LEN);

    // flash attention -> [b, s, h*HD]
    flash_kernel<<<dim3(S_LEN / 64, BATCH * NHQ), 256>>>((const float*)pQ, (const float*)pK, (const float*)pV, (float*)pA);

    // output projection
    gemm_tf32_kernel<<<dim3(HDIM / 128, M / 128), 256>>>((const float*)pA, Wo, out, M, HDIM, HDIM, 0, 0);
}

// round 13
// speedup vs baseline: 1.5375x; 1.5375x over previous
#include <cuda_runtime.h>
#include <cuda_bf16.h>
#include <cstdint>

#define BATCH 4
#define S_LEN 2048
#define HDIM  1024
#define NHQ   16
#define NKV   4
#define HD    64
#define SCALE 0.125f

// ---------------- device scratch (no cudaMalloc allowed) ----------------
__device__ float g_Q[(size_t)BATCH * NHQ * S_LEN * HD];    // [b, h, s, d]
__device__ float g_K[(size_t)BATCH * NKV * S_LEN * HD];    // [b, kvh, s, d]
__device__ float g_V[(size_t)BATCH * NKV * S_LEN * HD];    // [b, kvh, s, d]
__device__ float g_attn[(size_t)BATCH * S_LEN * NHQ * HD]; // [b, s, h*HD]

__device__ __align__(16) __nv_bfloat16 g_Xhi[(size_t)BATCH * S_LEN * HDIM];
__device__ __align__(16) __nv_bfloat16 g_Xlo[(size_t)BATCH * S_LEN * HDIM];
__device__ __align__(16) __nv_bfloat16 g_Ahi[(size_t)BATCH * S_LEN * HDIM];
__device__ __align__(16) __nv_bfloat16 g_Alo[(size_t)BATCH * S_LEN * HDIM];
__device__ __align__(16) __nv_bfloat16 g_Wqt_hi[(size_t)HDIM * HDIM];
__device__ __align__(16) __nv_bfloat16 g_Wqt_lo[(size_t)HDIM * HDIM];
__device__ __align__(16) __nv_bfloat16 g_Wkt_hi[(size_t)256 * HDIM];
__device__ __align__(16) __nv_bfloat16 g_Wkt_lo[(size_t)256 * HDIM];
__device__ __align__(16) __nv_bfloat16 g_Wvt_hi[(size_t)256 * HDIM];
__device__ __align__(16) __nv_bfloat16 g_Wvt_lo[(size_t)256 * HDIM];
__device__ __align__(16) __nv_bfloat16 g_Wot_hi[(size_t)HDIM * HDIM];
__device__ __align__(16) __nv_bfloat16 g_Wot_lo[(size_t)HDIM * HDIM];

// ---------------- bf16 mma.sync helper (legacy path, compiles on sm_103) --
__device__ __forceinline__ void mma_bf16(float c[4], const uint32_t a[4],
                                         uint32_t b0, uint32_t b1) {
    asm volatile(
        "mma.sync.aligned.m16n8k16.row.col.f32.bf16.bf16.f32 "
        "{%0,%1,%2,%3},{%4,%5,%6,%7},{%8,%9},{%0,%1,%2,%3};"
        : "+f"(c[0]), "+f"(c[1]), "+f"(c[2]), "+f"(c[3])
        : "r"(a[0]), "r"(a[1]), "r"(a[2]), "r"(a[3]), "r"(b0), "r"(b1));
}

// ---------------- 128x128 GEMM, 3-term bf16, K=1024 fixed -----------------
// C[M,N] = A[M,K] * Bt[N,K]^T with A = Ahi+Alo, B = Bhi+Blo (pre-split bf16)
// scatter==1: C is [b, head, s, d] (QKV projections); else row-major MxN.
#define SSTR 40   // smem row stride in halfwords (80 B): conflict-free frags

__global__ __launch_bounds__(256) void gemm_bf16_kernel(
    const __nv_bfloat16* __restrict__ Ahi, const __nv_bfloat16* __restrict__ Alo,
    const __nv_bfloat16* __restrict__ Bhi, const __nv_bfloat16* __restrict__ Blo,
    float* __restrict__ C, int N, int scatter, int heads)
{
    __shared__ __nv_bfloat16 sAh[128][SSTR], sAl[128][SSTR];
    __shared__ __nv_bfloat16 sBh[128][SSTR], sBl[128][SSTR];

    const int tid = threadIdx.x;
    const int lane = tid & 31, warp = tid >> 5;
    const int wm = warp & 3;     // 4 warps along M: 32 rows each
    const int wn = warp >> 2;    // 2 warps along N: 64 cols each
    const int bm = blockIdx.y << 7;
    const int bn = blockIdx.x << 7;

    // staging map: each thread owns row sr, halfword cols sc..sc+15 (two uint4)
    const int sr = tid >> 1;
    const int sc = (tid & 1) << 4;

    float acc[2][8][4];
#pragma unroll
    for (int mt = 0; mt < 2; mt++)
#pragma unroll
        for (int nt = 0; nt < 8; nt++)
#pragma unroll
            for (int e = 0; e < 4; e++) acc[mt][nt][e] = 0.f;

    const size_t aoff = (size_t)(bm + sr) * HDIM + sc;
    const size_t boff = (size_t)(bn + sr) * HDIM + sc;

    uint4 pAh[2], pAl[2], pBh[2], pBl[2];
    pAh[0] = *(const uint4*)(Ahi + aoff); pAh[1] = *(const uint4*)(Ahi + aoff + 8);
    pAl[0] = *(const uint4*)(Alo + aoff); pAl[1] = *(const uint4*)(Alo + aoff + 8);
    pBh[0] = *(const uint4*)(Bhi + boff); pBh[1] = *(const uint4*)(Bhi + boff + 8);
    pBl[0] = *(const uint4*)(Blo + boff); pBl[1] = *(const uint4*)(Blo + boff + 8);

    for (int k0 = 0; k0 < HDIM; k0 += 32) {
        // stage prefetched registers -> smem
        *(uint4*)(&sAh[sr][sc]) = pAh[0]; *(uint4*)(&sAh[sr][sc + 8]) = pAh[1];
        *(uint4*)(&sAl[sr][sc]) = pAl[0]; *(uint4*)(&sAl[sr][sc + 8]) = pAl[1];
        *(uint4*)(&sBh[sr][sc]) = pBh[0]; *(uint4*)(&sBh[sr][sc + 8]) = pBh[1];
        *(uint4*)(&sBl[sr][sc]) = pBl[0]; *(uint4*)(&sBl[sr][sc + 8]) = pBl[1];
        __syncthreads();

        if (k0 + 32 < HDIM) {  // prefetch next chunk
            const size_t na = aoff + k0 + 32, nb = boff + k0 + 32;
            pAh[0] = *(const uint4*)(Ahi + na); pAh[1] = *(const uint4*)(Ahi + na + 8);
            pAl[0] = *(const uint4*)(Alo + na); pAl[1] = *(const uint4*)(Alo + na + 8);
            pBh[0] = *(const uint4*)(Bhi + nb); pBh[1] = *(const uint4*)(Bhi + nb + 8);
            pBl[0] = *(const uint4*)(Blo + nb); pBl[1] = *(const uint4*)(Blo + nb + 8);
        }

#pragma unroll
        for (int ks = 0; ks < 32; ks += 16) {
            const int ca = ks + (lane & 3) * 2;
            uint32_t ah[2][4], al[2][4];
#pragma unroll
            for (int mt = 0; mt < 2; mt++) {
                const int r = wm * 32 + mt * 16 + (lane >> 2);
                ah[mt][0] = *(const uint32_t*)(&sAh[r][ca]);
                ah[mt][1] = *(const uint32_t*)(&sAh[r + 8][ca]);
                ah[mt][2] = *(const uint32_t*)(&sAh[r][ca + 8]);
                ah[mt][3] = *(const uint32_t*)(&sAh[r + 8][ca + 8]);
                al[mt][0] = *(const uint32_t*)(&sAl[r][ca]);
                al[mt][1] = *(const uint32_t*)(&sAl[r + 8][ca]);
                al[mt][2] = *(const uint32_t*)(&sAl[r][ca + 8]);
                al[mt][3] = *(const uint32_t*)(&sAl[r + 8][ca + 8]);
            }
#pragma unroll
            for (int nt = 0; nt < 8; nt++) {
                const int n = wn * 64 + nt * 8 + (lane >> 2);
                const uint32_t bh0 = *(const uint32_t*)(&sBh[n][ca]);
                const uint32_t bh1 = *(const uint32_t*)(&sBh[n][ca + 8]);
                const uint32_t bl0 = *(const uint32_t*)(&sBl[n][ca]);
                const uint32_t bl1 = *(const uint32_t*)(&sBl[n][ca + 8]);
#pragma unroll
                for (int mt = 0; mt < 2; mt++) {
                    mma_bf16(acc[mt][nt], ah[mt], bl0, bl1);  // small terms first
                    mma_bf16(acc[mt][nt], al[mt], bh0, bh1);
                    mma_bf16(acc[mt][nt], ah[mt], bh0, bh1);
                }
            }
        }
        __syncthreads();
    }

    // epilogue (fragment layout identical to m16n8k8: c0,c1 @ row r; c2,c3 @ r+8)
#pragma unroll
    for (int mt = 0; mt < 2; mt++) {
#pragma unroll
        for (int nt = 0; nt < 8; nt++) {
            const int r0 = bm + wm * 32 + mt * 16 + (lane >> 2);
            const int cn = bn + wn * 64 + nt * 8 + (lane & 3) * 2;
            if (scatter) {
                const int head = cn >> 6, d = cn & 63;
#pragma unroll
                for (int half = 0; half < 2; half++) {
                    const int rm = r0 + half * 8;
                    const int b = rm >> 11, s = rm & 2047;
                    float* dst = C + (((size_t)(b * heads + head)) * S_LEN + s) * HD + d;
                    *(float2*)dst = make_float2(acc[mt][nt][half * 2], acc[mt][nt][half * 2 + 1]);
                }
            } else {
                *(float2*)(C + (size_t)r0 * N + cn) =
                    make_float2(acc[mt][nt][0], acc[mt][nt][1]);
                *(float2*)(C + (size_t)(r0 + 8) * N + cn) =
                    make_float2(acc[mt][nt][2], acc[mt][nt][3]);
            }
        }
    }
}

// ---------------- fp32 -> bf16 hi/lo split ----------------
__global__ __launch_bounds__(256) void split_kernel(
    const float* __restrict__ X, __nv_bfloat16* __restrict__ Hi,
    __nv_bfloat16* __restrict__ Lo, int n4)
{
    const int i = blockIdx.x * 256 + threadIdx.x;
    if (i >= n4) return;
    const float4 v = ((const float4*)X)[i];
    float x[4] = {v.x, v.y, v.z, v.w};
    __nv_bfloat16 h[4], l[4];
#pragma unroll
    for (int e = 0; e < 4; e++) {
        h[e] = __float2bfloat16(x[e]);
        l[e] = __float2bfloat16(x[e] - __bfloat162float(h[e]));
    }
    ((__nv_bfloat162*)Hi)[2 * i]     = __nv_bfloat162(h[0], h[1]);
    ((__nv_bfloat162*)Hi)[2 * i + 1] = __nv_bfloat162(h[2], h[3]);
    ((__nv_bfloat162*)Lo)[2 * i]     = __nv_bfloat162(l[0], l[1]);
    ((__nv_bfloat162*)Lo)[2 * i + 1] = __nv_bfloat162(l[2], l[3]);
}

// ---------------- W[K,N] fp32 -> Wt[N,K] bf16 hi/lo (transpose+split) ------
__global__ __launch_bounds__(256) void transpose_split_kernel(
    const float* __restrict__ W, __nv_bfloat16* __restrict__ Thi,
    __nv_bfloat16* __restrict__ Tlo, int K, int N)
{
    __shared__ float t[32][33];
    const int k0 = blockIdx.y * 32, n0 = blockIdx.x * 32;
    const int tx = threadIdx.x, ty = threadIdx.y;   // 32 x 8
#pragma unroll
    for (int i = 0; i < 32; i += 8)
        t[ty + i][tx] = W[(size_t)(k0 + ty + i) * N + n0 + tx];
    __syncthreads();
#pragma unroll
    for (int i = 0; i < 32; i += 8) {
        const float x = t[tx][ty + i];
        const __nv_bfloat16 h = __float2bfloat16(x);
        const __nv_bfloat16 l = __float2bfloat16(x - __bfloat162float(h));
        Thi[(size_t)(n0 + ty + i) * K + k0 + tx] = h;
        Tlo[(size_t)(n0 + ty + i) * K + k0 + tx] = l;
    }
}

// ---------------- RMSNorm + interleaved RoPE ----------------
__global__ __launch_bounds__(256) void norm_rope_kernel(
    float* __restrict__ X, const float* __restrict__ w,
    const float* __restrict__ cosb, const float* __restrict__ sinb, int rows)
{
    const int row = blockIdx.x * 8 + threadIdx.y;
    if (row >= rows) return;
    const int lane = threadIdx.x;
    const int s = row & (S_LEN - 1);

    float2 x = *(float2*)(X + (size_t)row * HD + lane * 2);
    float ssq = x.x * x.x + x.y * x.y;
#pragma unroll
    for (int m = 16; m; m >>= 1) ssq += __shfl_xor_sync(0xffffffffu, ssq, m);
    const float inv = rsqrtf(ssq * (1.0f / 64.0f) + 1e-6f);

    const float n0 = x.x * inv * w[lane * 2];
    const float n1 = x.y * inv * w[lane * 2 + 1];
    const float c0 = cosb[(size_t)s * HD + lane * 2];
    const float c1 = cosb[(size_t)s * HD + lane * 2 + 1];
    const float s0 = sinb[(size_t)s * HD + lane * 2];
    const float s1 = sinb[(size_t)s * HD + lane * 2 + 1];

    float2 o;
    o.x = n0 * c0 - n1 * s0;
    o.y = n1 * c1 + n0 * s1;
    *(float2*)(X + (size_t)row * HD + lane * 2) = o;
}

// ---------------- flash attention (causal, GQA), fp32 ----------------
__global__ __launch_bounds__(256) void flash_kernel(
    const float* __restrict__ Q, const float* __restrict__ K,
    const float* __restrict__ V, float* __restrict__ O)
{
    __shared__ float QsT[64][64];
    __shared__ float KsT[64][64];
    __shared__ float Vs[64][64];
    float (*Ps)[64] = KsT;

    const int bh = blockIdx.y;
    const int b = bh >> 4, h = bh & 15, kvh = (bh & 15) >> 2;
    const int i0 = blockIdx.x << 6;
    const float* Qb = Q + ((size_t)(b * NHQ + h) * S_LEN + i0) * HD;
    const float* Kb = K + (size_t)(b * NKV + kvh) * S_LEN * HD;
    const float* Vb = V + (size_t)(b * NKV + kvh) * S_LEN * HD;

    const int tid = threadIdx.x;
    const int tx = tid & 15, ty = tid >> 4;
    const int r0 = ty << 2, c0 = tx << 2;

    for (int idx = tid; idx < 1024; idx += 256) {
        const int r = idx >> 4, d = (idx & 15) << 2;
        float4 v = *(const float4*)(Qb + (size_t)r * HD + d);
        QsT[d][r] = v.x; QsT[d + 1][r] = v.y; QsT[d + 2][r] = v.z; QsT[d + 3][r] = v.w;
    }

    float m_i[4] = {-1e30f, -1e30f, -1e30f, -1e30f};
    float l_i[4] = {0.f, 0.f, 0.f, 0.f};
    float oa[4][4];
#pragma unroll
    for (int i = 0; i < 4; i++)
#pragma unroll
        for (int j = 0; j < 4; j++) oa[i][j] = 0.f;

    const int ntiles = blockIdx.x + 1;
    for (int t = 0; t < ntiles; t++) {
        const int j0 = t << 6;
        __syncthreads();
        for (int idx = tid; idx < 1024; idx += 256) {
            const int r = idx >> 4, d = (idx & 15) << 2;
            float4 kv = *(const float4*)(Kb + (size_t)(j0 + r) * HD + d);
            KsT[d][r] = kv.x; KsT[d + 1][r] = kv.y; KsT[d + 2][r] = kv.z; KsT[d + 3][r] = kv.w;
            *(float4*)(&Vs[r][d]) = *(const float4*)(Vb + (size_t)(j0 + r) * HD + d);
        }
        __syncthreads();

        float sc[4][4];
#pragma unroll
        for (int i = 0; i < 4; i++)
#pragma unroll
            for (int j = 0; j < 4; j++) sc[i][j] = 0.f;
#pragma unroll 8
        for (int d = 0; d < 64; d++) {
            float4 aq = *(const float4*)(&QsT[d][r0]);
            float4 bk = *(const float4*)(&KsT[d][c0]);
            sc[0][0] += aq.x * bk.x; sc[0][1] += aq.x * bk.y; sc[0][2] += aq.x * bk.z; sc[0][3] += aq.x * bk.w;
            sc[1][0] += aq.y * bk.x; sc[1][1] += aq.y * bk.y; sc[1][2] += aq.y * bk.z; sc[1][3] += aq.y * bk.w;
            sc[2][0] += aq.z * bk.x; sc[2][1] += aq.z * bk.y; sc[2][2] += aq.z * bk.z; sc[2][3] += aq.z * bk.w;
            sc[3][0] += aq.w * bk.x; sc[3][1] += aq.w * bk.y; sc[3][2] += aq.w * bk.z; sc[3][3] += aq.w * bk.w;
        }
        __syncthreads();

        const bool diag = (t == (int)blockIdx.x);
#pragma unroll
        for (int i = 0; i < 4; i++) {
#pragma unroll
            for (int j = 0; j < 4; j++) {
                float s = sc[i][j] * SCALE;
                if (diag && (c0 + j > r0 + i)) s = -1e9f;
                sc[i][j] = s;
            }
            float mt = fmaxf(fmaxf(sc[i][0], sc[i][1]), fmaxf(sc[i][2], sc[i][3]));
            mt = fmaxf(mt, __shfl_xor_sync(0xffffffffu, mt, 8));
            mt = fmaxf(mt, __shfl_xor_sync(0xffffffffu, mt, 4));
            mt = fmaxf(mt, __shfl_xor_sync(0xffffffffu, mt, 2));
            mt = fmaxf(mt, __shfl_xor_sync(0xffffffffu, mt, 1));
            const float m_new = fmaxf(m_i[i], mt);
            const float corr = __expf(m_i[i] - m_new);
            m_i[i] = m_new;
            float ps = 0.f;
#pragma unroll
            for (int j = 0; j < 4; j++) {
                const float p = __expf(sc[i][j] - m_new);
                sc[i][j] = p;
                ps += p;
            }
            ps += __shfl_xor_sync(0xffffffffu, ps, 8);
            ps += __shfl_xor_sync(0xffffffffu, ps, 4);
            ps += __shfl_xor_sync(0xffffffffu, ps, 2);
            ps += __shfl_xor_sync(0xffffffffu, ps, 1);
            l_i[i] = l_i[i] * corr + ps;
#pragma unroll
            for (int j = 0; j < 4; j++) oa[i][j] *= corr;
            *(float4*)(&Ps[r0 + i][c0]) = *(float4*)(&sc[i][0]);
        }
        __syncthreads();

#pragma unroll 8
        for (int k = 0; k < 64; k++) {
            float4 vv = *(const float4*)(&Vs[k][c0]);
#pragma unroll
            for (int i = 0; i < 4; i++) {
                const float p = Ps[r0 + i][k];
                oa[i][0] += p * vv.x; oa[i][1] += p * vv.y;
                oa[i][2] += p * vv.z; oa[i][3] += p * vv.w;
            }
        }
    }

#pragma unroll
    for (int i = 0; i < 4; i++) {
        const float inv = 1.0f / l_i[i];
        float* dst = O + ((size_t)b * S_LEN + i0 + r0 + i) * (NHQ * HD) + h * HD + c0;
        *(float4*)dst = make_float4(oa[i][0] * inv, oa[i][1] * inv,
                                    oa[i][2] * inv, oa[i][3] * inv);
    }
}

// ---------------- launch ----------------
extern "C" void kernel_launch(void* const* d_in, const int* in_sizes, int n_in,
                              void* d_out, int out_size)
{
    const float* X    = (const float*)d_in[0];
    const float* cosb = (const float*)d_in[2];
    const float* sinb = (const float*)d_in[3];
    const float* Wq   = (const float*)d_in[4];
    const float* Wk   = (const float*)d_in[5];
    const float* Wv   = (const float*)d_in[6];
    const float* Wo   = (const float*)d_in[7];
    const float* qw   = (const float*)d_in[8];
    const float* kw   = (const float*)d_in[9];
    float* out = (float*)d_out;

    void *pQ, *pK, *pV, *pA;
    void *pXhi, *pXlo, *pAhi, *pAlo;
    void *pWq_h, *pWq_l, *pWk_h, *pWk_l, *pWv_h, *pWv_l, *pWo_h, *pWo_l;
    cudaGetSymbolAddress(&pQ, g_Q);
    cudaGetSymbolAddress(&pK, g_K);
    cudaGetSymbolAddress(&pV, g_V);
    cudaGetSymbolAddress(&pA, g_attn);
    cudaGetSymbolAddress(&pXhi, g_Xhi);
    cudaGetSymbolAddress(&pXlo, g_Xlo);
    cudaGetSymbolAddress(&pAhi, g_Ahi);
    cudaGetSymbolAddress(&pAlo, g_Alo);
    cudaGetSymbolAddress(&pWq_h, g_Wqt_hi);
    cudaGetSymbolAddress(&pWq_l, g_Wqt_lo);
    cudaGetSymbolAddress(&pWk_h, g_Wkt_hi);
    cudaGetSymbolAddress(&pWk_l, g_Wkt_lo);
    cudaGetSymbolAddress(&pWv_h, g_Wvt_hi);
    cudaGetSymbolAddress(&pWv_l, g_Wvt_lo);
    cudaGetSymbolAddress(&pWo_h, g_Wot_hi);
    cudaGetSymbolAddress(&pWo_l, g_Wot_lo);

    const int M = BATCH * S_LEN;          // 8192
    const int n4 = M * HDIM / 4;          // float4 count

    // splits / transposes
    split_kernel<<<(n4 + 255) / 256, 256>>>(X, (__nv_bfloat16*)pXhi, (__nv_bfloat16*)pXlo, n4);
    transpose_split_kernel<<<dim3(HDIM / 32, HDIM / 32), dim3(32, 8)>>>(Wq, (__nv_bfloat16*)pWq_h, (__nv_bfloat16*)pWq_l, HDIM, HDIM);
    transpose_split_kernel<<<dim3(256 / 32, HDIM / 32), dim3(32, 8)>>>(Wk, (__nv_bfloat16*)pWk_h, (__nv_bfloat16*)pWk_l, HDIM, 256);
    transpose_split_kernel<<<dim3(256 / 32, HDIM / 32), dim3(32, 8)>>>(Wv, (__nv_bfloat16*)pWv_h, (__nv_bfloat16*)pWv_l, HDIM, 256);
    transpose_split_kernel<<<dim3(HDIM / 32, HDIM / 32), dim3(32, 8)>>>(Wo, (__nv_bfloat16*)pWo_h, (__nv_bfloat16*)pWo_l, HDIM, HDIM);

    // QKV projections (bf16 mma.sync), scatter into [b, head, s, d]
    gemm_bf16_kernel<<<dim3(NHQ * HD / 128, M / 128), 256>>>(
        (const __nv_bfloat16*)pXhi, (const __nv_bfloat16*)pXlo,
        (const __nv_bfloat16*)pWq_h, (const __nv_bfloat16*)pWq_l,
        (float*)pQ, NHQ * HD, 1, NHQ);
    gemm_bf16_kernel<<<dim3(NKV * HD / 128, M / 128), 256>>>(
        (const __nv_bfloat16*)pXhi, (const __nv_bfloat16*)pXlo,
        (const __nv_bfloat16*)pWk_h, (const __nv_bfloat16*)pWk_l,
        (float*)pK, NKV * HD, 1, NKV);
    gemm_bf16_kernel<<<dim3(NKV * HD / 128, M / 128), 256>>>(
        (const __nv_bfloat16*)pXhi, (const __nv_bfloat16*)pXlo,
        (const __nv_bfloat16*)pWv_h, (const __nv_bfloat16*)pWv_l,
        (float*)pV, NKV * HD, 1, NKV);

    // RMSNorm + RoPE
    norm_rope_kernel<<<(BATCH * NHQ * S_LEN) / 8, dim3(32, 8)>>>((float*)pQ, qw, cosb, sinb, BATCH * NHQ * S_LEN);
    norm_rope_kernel<<<(BATCH * NKV * S_LEN) / 8, dim3(32, 8)>>>((float*)pK, kw, cosb, sinb, BATCH * NKV * S_LEN);

    // flash attention (fp32)
    flash_kernel<<<dim3(S_LEN / 64, BATCH * NHQ), 256>>>((const float*)pQ, (const float*)pK, (const float*)pV, (float*)pA);

    // split attn, then O-projection (bf16 mma.sync)
    split_kernel<<<(n4 + 255) / 256, 256>>>((const float*)pA, (__nv_bfloat16*)pAhi, (__nv_bfloat16*)pAlo, n4);
    gemm_bf16_kernel<<<dim3(HDIM / 128, M / 128), 256>>>(
        (const __nv_bfloat16*)pAhi, (const __nv_bfloat16*)pAlo,
        (const __nv_bfloat16*)pWo_h, (const __nv_bfloat16*)pWo_l,
        out, HDIM, 0, 0);
}